// round 16
// baseline (speedup 1.0000x reference)
#include <cuda_runtime.h>
#include <cuda_bf16.h>
#include <math.h>

#define BATCH 4
#define CH 128
#define NTOK 4096            // H*W
#define M_ROWS (BATCH*NTOK)  // 16384
#define HEADS 4
#define HD 32
#define HIDDEN 256
#define EPS 1e-5f

// q pre-scale: (1/sqrt(32)) * log2(e)  -> softmax done in exp2 domain
#define QSC (0.17677669529663689f * 1.4426950408889634f)

// ---------------- scratch (device globals; no allocation) ----------------
__device__ __nv_bfloat16  g_xln [M_ROWS * CH];
__device__ float          g_xtok[M_ROWS * CH];
__device__ __nv_bfloat16  g_qkv [M_ROWS * 3 * CH];
__device__ __nv_bfloat16  g_vT  [BATCH * HEADS * HD * NTOK];
__device__ __nv_bfloat16  g_attn[M_ROWS * CH];
__device__ __nv_bfloat16  g_wqkv[3 * CH * CH];
__device__ __nv_bfloat16  g_wproj[CH * CH];
__device__ __nv_bfloat16  g_wfc1[HIDDEN * CH];
__device__ __nv_bfloat16  g_wfc2[CH * HIDDEN];

__device__ __forceinline__ unsigned ex2b(unsigned x) {
    unsigned r;
    asm("ex2.approx.ftz.bf16x2 %0, %1;" : "=r"(r) : "r"(x));
    return r;
}

__device__ __forceinline__ unsigned smem_u32(const void* p) {
    return (unsigned)__cvta_generic_to_shared(p);
}

#define CP16(dst, src) \
    asm volatile("cp.async.cg.shared.global [%0], [%1], 16;" :: "r"(dst), "l"(src))
#define CPCOMMIT() asm volatile("cp.async.commit_group;")
#define CPWAIT0()  asm volatile("cp.async.wait_group 0;")

#define LDSM4(r0, r1, r2, r3, addr) \
    asm volatile("ldmatrix.sync.aligned.m8n8.x4.shared.b16 {%0,%1,%2,%3}, [%4];" \
                 : "=r"(r0), "=r"(r1), "=r"(r2), "=r"(r3) : "r"(addr))

__device__ __forceinline__ void mma16816(float d[4], const unsigned a[4],
                                         unsigned b0, unsigned b1) {
    asm volatile(
        "mma.sync.aligned.m16n8k16.row.col.f32.bf16.bf16.f32 "
        "{%0,%1,%2,%3}, {%4,%5,%6,%7}, {%8,%9}, {%0,%1,%2,%3};"
        : "+f"(d[0]), "+f"(d[1]), "+f"(d[2]), "+f"(d[3])
        : "r"(a[0]), "r"(a[1]), "r"(a[2]), "r"(a[3]), "r"(b0), "r"(b1));
}

// ---------------- LN1 (+ fused weight fp32->bf16 conversion) -------------
__global__ void ln1_kernel(const float* __restrict__ x,
                           const float* __restrict__ w,
                           const float* __restrict__ bgain,
                           const float* __restrict__ qkv_w,
                           const float* __restrict__ proj_w,
                           const float* __restrict__ fc1_w,
                           const float* __restrict__ fc2_w) {
    if (blockIdx.x >= 512) {
        int i = (blockIdx.x - 512) * 256 + threadIdx.x;
        if (i < 49152)       g_wqkv[i]          = __float2bfloat16(qkv_w[i]);
        else if (i < 65536)  g_wproj[i - 49152] = __float2bfloat16(proj_w[i - 49152]);
        else if (i < 98304)  g_wfc1[i - 65536]  = __float2bfloat16(fc1_w[i - 65536]);
        else if (i < 131072) g_wfc2[i - 98304]  = __float2bfloat16(fc2_w[i - 98304]);
        return;
    }

    __shared__ float s[CH][33];
    __shared__ float ps[8][32], pq[8][32];
    __shared__ float mu_s[32], rs_s[32];

    int b  = blockIdx.x >> 7;
    int n0 = (blockIdx.x & 127) * 32;
    int tx = threadIdx.x & 31;
    int ty = threadIdx.x >> 5;

    const float* xb = x + (size_t)b * CH * NTOK + n0;
    float sum = 0.f, sq = 0.f;
#pragma unroll
    for (int c = ty; c < CH; c += 8) {
        float v = xb[(size_t)c * NTOK + tx];
        s[c][tx] = v;
        sum += v; sq += v * v;
    }
    ps[ty][tx] = sum; pq[ty][tx] = sq;
    __syncthreads();
    if (ty == 0) {
        float S = 0.f, Q = 0.f;
#pragma unroll
        for (int i = 0; i < 8; i++) { S += ps[i][tx]; Q += pq[i][tx]; }
        float mu  = S * (1.0f / CH);
        float var = Q * (1.0f / CH) - mu * mu;
        mu_s[tx] = mu;
        rs_s[tx] = rsqrtf(var + EPS);
    }
    __syncthreads();
    __nv_bfloat16* out = g_xln + ((size_t)b * NTOK + n0) * CH;
    float* outraw = g_xtok + ((size_t)b * NTOK + n0) * CH;
    for (int idx = threadIdx.x; idx < 32 * CH; idx += 256) {
        int t = idx >> 7, c = idx & 127;
        float raw = s[c][t];
        outraw[idx] = raw;
        out[idx] = __float2bfloat16((raw - mu_s[t]) * rs_s[t] * w[c] + bgain[c]);
    }
}

// ---------------- QKV tensor-core GEMM (cp.async double-buffered) --------
#define GA_STRIDE (128 * 40 * 2)
#define GW_STRIDE (64 * 40 * 2)

__global__ __launch_bounds__(256)
void gemm_qkv(const __nv_bfloat16* __restrict__ A,
              const __nv_bfloat16* __restrict__ W, int K) {
    __shared__ __nv_bfloat16 As[2][128][40];
    __shared__ __nv_bfloat16 Ws[2][64][40];

    int m0 = blockIdx.y * 128;
    int n0 = blockIdx.x * 64;
    int tid  = threadIdx.x;
    int warp = tid >> 5;
    int lane = tid & 31;
    int g = lane >> 2;
    int t = lane & 3;
    int warp_m = warp >> 1;
    int warp_n = warp & 1;

    float acc[2][4][4];
#pragma unroll
    for (int i = 0; i < 2; i++)
#pragma unroll
        for (int j = 0; j < 4; j++)
#pragma unroll
            for (int c = 0; c < 4; c++) acc[i][j][c] = 0.f;

    int arow = tid >> 2, achk = tid & 3;
    const __nv_bfloat16* ag0 = A + (size_t)(m0 + arow) * K + achk * 8;
    const __nv_bfloat16* ag1 = A + (size_t)(m0 + arow + 64) * K + achk * 8;
    const __nv_bfloat16* wg  = W + (size_t)(n0 + arow) * K + achk * 8;
    unsigned asd = smem_u32(&As[0][arow][achk * 8]);
    unsigned wsd = smem_u32(&Ws[0][arow][achk * 8]);

    CP16(asd, ag0);
    CP16(asd + 64 * 80, ag1);
    CP16(wsd, wg);
    CPCOMMIT();

    int buf = 0;
    for (int k0 = 0; k0 < K; k0 += 32) {
        CPWAIT0();
        __syncthreads();
        if (k0 + 32 < K) {
            int nb = buf ^ 1;
            CP16(asd + nb * GA_STRIDE, ag0 + k0 + 32);
            CP16(asd + nb * GA_STRIDE + 64 * 80, ag1 + k0 + 32);
            CP16(wsd + nb * GW_STRIDE, wg + k0 + 32);
            CPCOMMIT();
        }

#pragma unroll
        for (int kk = 0; kk < 2; kk++) {
            unsigned af[2][4];
#pragma unroll
            for (int i = 0; i < 2; i++) {
                int r = warp_m * 32 + i * 16 + g;
                af[i][0] = *(const unsigned*)&As[buf][r][kk * 16 + 2 * t];
                af[i][1] = *(const unsigned*)&As[buf][r + 8][kk * 16 + 2 * t];
                af[i][2] = *(const unsigned*)&As[buf][r][kk * 16 + 2 * t + 8];
                af[i][3] = *(const unsigned*)&As[buf][r + 8][kk * 16 + 2 * t + 8];
            }
#pragma unroll
            for (int j = 0; j < 4; j++) {
                int wr = warp_n * 32 + j * 8 + g;
                unsigned b0 = *(const unsigned*)&Ws[buf][wr][kk * 16 + 2 * t];
                unsigned b1 = *(const unsigned*)&Ws[buf][wr][kk * 16 + 2 * t + 8];
                mma16816(acc[0][j], af[0], b0, b1);
                mma16816(acc[1][j], af[1], b0, b1);
            }
        }
        buf ^= 1;
    }

#pragma unroll
    for (int i = 0; i < 2; i++) {
#pragma unroll
        for (int j = 0; j < 4; j++) {
            int col = n0 + warp_n * 32 + j * 8 + 2 * t;
#pragma unroll
            for (int half = 0; half < 2; half++) {
                int row = m0 + warp_m * 32 + i * 16 + g + half * 8;
                float v0 = acc[i][j][2 * half + 0];
                float v1 = acc[i][j][2 * half + 1];
                int b = row >> 12;
                int n = row & (NTOK - 1);
                if (col < CH) {
                    __nv_bfloat162 p = __floats2bfloat162_rn(v0 * QSC, v1 * QSC);
                    *(__nv_bfloat162*)&g_qkv[(size_t)row * (3 * CH) + col] = p;
                } else if (col < 2 * CH) {
                    __nv_bfloat162 p = __floats2bfloat162_rn(v0, v1);
                    *(__nv_bfloat162*)&g_qkv[(size_t)row * (3 * CH) + col] = p;
                } else {
                    int hh = (col - 2 * CH) >> 5;
                    int d  = (col - 2 * CH) & 31;
                    size_t base = (((size_t)(b * HEADS + hh)) * HD + d) * NTOK + n;
                    g_vT[base]        = __float2bfloat16(v0);
                    g_vT[base + NTOK] = __float2bfloat16(v1);
                }
            }
        }
    }
}

// ---------------- fused tail (BM=32, 3 CTAs/SM): proj+LN2+fc1+gelu+fc2 ---
// 256 threads, 8 warps as 2 (warp_m) x 4 (warp_n). x2 stays in registers.
// Dynamic smem layout (bytes):
//   [0, 40960)       R1: weights dbuf (proj As1+Wsp / fc1 Ws1 / fc2 Ws2)
//   [40960, 43008)   red_s/red_q (32 x 4 fp32 each)
//   [43008, 51712)   xln_s [32][136] bf16
//   [51712, 68608)   Hs    [32][264] bf16
#define TAIL_SMEM 68608
#define PA_STRIDE (32 * 40 * 2)
#define PW_STRIDE (128 * 40 * 2)
#define WS1_STRIDE (256 * 40 * 2)
#define WS2_STRIDE (128 * 40 * 2)
#define XSTR 136
#define HSTR 264

__global__ __launch_bounds__(256, 3)
void tail_kernel(const __nv_bfloat16* __restrict__ Aattn,
                 const float* __restrict__ pbias,
                 const float* __restrict__ resx,     // xtok fp32
                 const float* __restrict__ w2,       // ln2 w
                 const float* __restrict__ b2,       // ln2 b
                 const float* __restrict__ b1,       // fc1 bias
                 const float* __restrict__ b2v,      // fc2 bias
                 float* __restrict__ C) {
    extern __shared__ char dsm[];
    __nv_bfloat16* As1  = (__nv_bfloat16*)dsm;               // proj A [2][32][40]
    __nv_bfloat16* Wsp  = (__nv_bfloat16*)(dsm + 5120);      // proj W [2][128][40]
    __nv_bfloat16* Ws1  = (__nv_bfloat16*)dsm;               // fc1 W [2][256][40]
    __nv_bfloat16* Ws2  = (__nv_bfloat16*)dsm;               // fc2 W [2][128][40]
    float* red_s = (float*)(dsm + 40960);                    // [32][4]
    float* red_q = (float*)(dsm + 41984);                    // [32][4]
    __nv_bfloat16* xln_s = (__nv_bfloat16*)(dsm + 43008);    // [32][136]
    __nv_bfloat16* Hs    = (__nv_bfloat16*)(dsm + 51712);    // [32][264]

    int m0 = blockIdx.x * 32;
    int tid  = threadIdx.x;
    int warp = tid >> 5;
    int lane = tid & 31;
    int g = lane >> 2;
    int t = lane & 3;
    int warp_m = warp >> 2;   // 0..1 (16-row tiles)
    int warp_n = warp & 3;    // 0..3

    int arow = tid >> 2, achk = tid & 3;      // weight loader: 64 rows x 4 chunks
    int a2row = (tid & 127) >> 2;             // A loader (rows 0..31, tid<128)

    // per-thread loader bases for each weight set
    const __nv_bfloat16* w1g = g_wfc1 + (size_t)arow * CH + achk * 8;
    unsigned ws1d = smem_u32(Ws1 + arow * 40 + achk * 8);
    const __nv_bfloat16* w2g = g_wfc2 + (size_t)arow * HIDDEN + achk * 8;
    unsigned ws2d = smem_u32(Ws2 + arow * 40 + achk * 8);

    // ================= phase 1: proj GEMM =================
    float acc[4][4];
#pragma unroll
    for (int j = 0; j < 4; j++)
#pragma unroll
        for (int c = 0; c < 4; c++) acc[j][c] = 0.f;

    {
        const __nv_bfloat16* ag  = Aattn + (size_t)(m0 + a2row) * CH + achk * 8;
        const __nv_bfloat16* wg0 = g_wproj + (size_t)arow * CH + achk * 8;
        const __nv_bfloat16* wg1 = g_wproj + (size_t)(arow + 64) * CH + achk * 8;
        unsigned asd = smem_u32(As1 + a2row * 40 + achk * 8);
        unsigned wsd = smem_u32(Wsp + arow * 40 + achk * 8);

        if (tid < 128) CP16(asd, ag);
        CP16(wsd, wg0);
        CP16(wsd + 64 * 80, wg1);
        CPCOMMIT();

        int buf = 0;
        for (int k0 = 0; k0 < CH; k0 += 32) {
            CPWAIT0();
            __syncthreads();
            if (k0 + 32 < CH) {
                int nb = buf ^ 1;
                if (tid < 128) CP16(asd + nb * PA_STRIDE, ag + k0 + 32);
                CP16(wsd + nb * PW_STRIDE, wg0 + k0 + 32);
                CP16(wsd + nb * PW_STRIDE + 64 * 80, wg1 + k0 + 32);
                CPCOMMIT();
            }
#pragma unroll
            for (int kk = 0; kk < 2; kk++) {
                unsigned af[4];
                const __nv_bfloat16* Ab = As1 + (size_t)buf * (32 * 40);
                int r = warp_m * 16 + g;
                af[0] = *(const unsigned*)&Ab[r * 40 + kk * 16 + 2 * t];
                af[1] = *(const unsigned*)&Ab[(r + 8) * 40 + kk * 16 + 2 * t];
                af[2] = *(const unsigned*)&Ab[r * 40 + kk * 16 + 2 * t + 8];
                af[3] = *(const unsigned*)&Ab[(r + 8) * 40 + kk * 16 + 2 * t + 8];
                const __nv_bfloat16* Wb = Wsp + (size_t)buf * (128 * 40);
#pragma unroll
                for (int j = 0; j < 4; j++) {
                    int wr = warp_n * 32 + j * 8 + g;
                    unsigned b0 = *(const unsigned*)&Wb[wr * 40 + kk * 16 + 2 * t];
                    unsigned b1f = *(const unsigned*)&Wb[wr * 40 + kk * 16 + 2 * t + 8];
                    mma16816(acc[j], af, b0, b1f);
                }
            }
            buf ^= 1;
        }
    }

    // hoisted fc1 stage-0 prologue: retire proj's reads of R1, then load
    __syncthreads();
#pragma unroll
    for (int i = 0; i < 4; i++)
        CP16(ws1d + i * 64 * 80, w1g + (size_t)i * 64 * CH);
    CPCOMMIT();

    // ---- proj epilogue: +bias +res -> acc (x2 in regs), LN2 -> xln_s ----
    float s[2] = {0.f, 0.f}, q[2] = {0.f, 0.f};
#pragma unroll
    for (int j = 0; j < 4; j++) {
        int col = warp_n * 32 + j * 8 + 2 * t;
#pragma unroll
        for (int h = 0; h < 2; h++) {
            int row = m0 + warp_m * 16 + g + h * 8;
            float2 rv = *(const float2*)&resx[(size_t)row * CH + col];
            float r0 = acc[j][2 * h]     + pbias[col]     + rv.x;
            float r1 = acc[j][2 * h + 1] + pbias[col + 1] + rv.y;
            acc[j][2 * h]     = r0;
            acc[j][2 * h + 1] = r1;
            s[h] += r0 + r1;
            q[h] += r0 * r0 + r1 * r1;
        }
    }
#pragma unroll
    for (int h = 0; h < 2; h++) {
        s[h] += __shfl_xor_sync(0xffffffffu, s[h], 1);
        s[h] += __shfl_xor_sync(0xffffffffu, s[h], 2);
        q[h] += __shfl_xor_sync(0xffffffffu, q[h], 1);
        q[h] += __shfl_xor_sync(0xffffffffu, q[h], 2);
    }
    if (t == 0) {
#pragma unroll
        for (int h = 0; h < 2; h++) {
            int rl = warp_m * 16 + g + h * 8;
            red_s[rl * 4 + warp_n] = s[h];
            red_q[rl * 4 + warp_n] = q[h];
        }
    }
    __syncthreads();

    float mu[2], rs[2];
#pragma unroll
    for (int h = 0; h < 2; h++) {
        int rl = warp_m * 16 + g + h * 8;
        float S = red_s[rl * 4] + red_s[rl * 4 + 1] + red_s[rl * 4 + 2] + red_s[rl * 4 + 3];
        float Q = red_q[rl * 4] + red_q[rl * 4 + 1] + red_q[rl * 4 + 2] + red_q[rl * 4 + 3];
        mu[h] = S * (1.0f / CH);
        float var = Q * (1.0f / CH) - mu[h] * mu[h];
        rs[h] = rsqrtf(var + EPS);
    }

#pragma unroll
    for (int j = 0; j < 4; j++) {
        int col = warp_n * 32 + j * 8 + 2 * t;
        float2 wv = *(const float2*)&w2[col];
        float2 bv = *(const float2*)&b2[col];
#pragma unroll
        for (int h = 0; h < 2; h++) {
            int rl  = warp_m * 16 + g + h * 8;
            float r0 = acc[j][2 * h];
            float r1 = acc[j][2 * h + 1];
            __nv_bfloat162 p = __floats2bfloat162_rn(
                (r0 - mu[h]) * rs[h] * wv.x + bv.x,
                (r1 - mu[h]) * rs[h] * wv.y + bv.y);
            *(__nv_bfloat162*)&xln_s[rl * XSTR + col] = p;
        }
    }
    __syncthreads();   // xln_s complete

    // ================= phase 2: fc1 + gelu -> Hs =================
    float acc1[8][4];
#pragma unroll
    for (int j = 0; j < 8; j++)
#pragma unroll
        for (int c = 0; c < 4; c++) acc1[j][c] = 0.f;

    {
        int buf = 0;
        for (int k0 = 0; k0 < CH; k0 += 32) {
            CPWAIT0();
            __syncthreads();
            if (k0 + 32 < CH) {
                int nb = buf ^ 1;
#pragma unroll
                for (int i = 0; i < 4; i++)
                    CP16(ws1d + nb * WS1_STRIDE + i * 64 * 80,
                         w1g + (size_t)i * 64 * CH + k0 + 32);
                CPCOMMIT();
            }
#pragma unroll
            for (int kk = 0; kk < 2; kk++) {
                unsigned af[4];
                int r = warp_m * 16 + g;
                int kc = k0 + kk * 16 + 2 * t;
                af[0] = *(const unsigned*)&xln_s[r * XSTR + kc];
                af[1] = *(const unsigned*)&xln_s[(r + 8) * XSTR + kc];
                af[2] = *(const unsigned*)&xln_s[r * XSTR + kc + 8];
                af[3] = *(const unsigned*)&xln_s[(r + 8) * XSTR + kc + 8];
                const __nv_bfloat16* Wb = Ws1 + (size_t)buf * (256 * 40);
#pragma unroll
                for (int j = 0; j < 8; j++) {
                    int wr = warp_n * 64 + j * 8 + g;
                    unsigned b0 = *(const unsigned*)&Wb[wr * 40 + kk * 16 + 2 * t];
                    unsigned b1f = *(const unsigned*)&Wb[wr * 40 + kk * 16 + 2 * t + 8];
                    mma16816(acc1[j], af, b0, b1f);
                }
            }
            buf ^= 1;
        }
    }

    // hoisted fc2 stage-0 prologue: Ws2 slot0 (0..10240) disjoint from
    // fc1 slot1 (20480..40960) still being read.
    CP16(ws2d, w2g);
    CP16(ws2d + 64 * 80, w2g + (size_t)64 * HIDDEN);
    CPCOMMIT();

    // fc1 epilogue: bias + gelu -> Hs
#pragma unroll
    for (int j = 0; j < 8; j++) {
        int col = warp_n * 64 + j * 8 + 2 * t;
#pragma unroll
        for (int h = 0; h < 2; h++) {
            int rl = warp_m * 16 + g + h * 8;
            float r0 = acc1[j][2 * h]     + b1[col];
            float r1 = acc1[j][2 * h + 1] + b1[col + 1];
            r0 = 0.5f * r0 * (1.0f + erff(r0 * 0.70710678118654752f));
            r1 = 0.5f * r1 * (1.0f + erff(r1 * 0.70710678118654752f));
            __nv_bfloat162 p = __floats2bfloat162_rn(r0, r1);
            *(__nv_bfloat162*)&Hs[rl * HSTR + col] = p;
        }
    }
    __syncthreads();   // Hs complete

    // ================= phase 3: fc2 + b2 + x2(regs) -> out =================
    float acc2[4][4];
#pragma unroll
    for (int j = 0; j < 4; j++)
#pragma unroll
        for (int c = 0; c < 4; c++) acc2[j][c] = 0.f;

    {
        int buf = 0;
        for (int k0 = 0; k0 < HIDDEN; k0 += 32) {
            CPWAIT0();
            __syncthreads();
            if (k0 + 32 < HIDDEN) {
                int nb = buf ^ 1;
                CP16(ws2d + nb * WS2_STRIDE, w2g + k0 + 32);
                CP16(ws2d + nb * WS2_STRIDE + 64 * 80,
                     w2g + (size_t)64 * HIDDEN + k0 + 32);
                CPCOMMIT();
            }
#pragma unroll
            for (int kk = 0; kk < 2; kk++) {
                unsigned af[4];
                int r = warp_m * 16 + g;
                int kc = k0 + kk * 16 + 2 * t;
                af[0] = *(const unsigned*)&Hs[r * HSTR + kc];
                af[1] = *(const unsigned*)&Hs[(r + 8) * HSTR + kc];
                af[2] = *(const unsigned*)&Hs[r * HSTR + kc + 8];
                af[3] = *(const unsigned*)&Hs[(r + 8) * HSTR + kc + 8];
                const __nv_bfloat16* Wb = Ws2 + (size_t)buf * (128 * 40);
#pragma unroll
                for (int j = 0; j < 4; j++) {
                    int wr = warp_n * 32 + j * 8 + g;
                    unsigned b0 = *(const unsigned*)&Wb[wr * 40 + kk * 16 + 2 * t];
                    unsigned b1f = *(const unsigned*)&Wb[wr * 40 + kk * 16 + 2 * t + 8];
                    mma16816(acc2[j], af, b0, b1f);
                }
            }
            buf ^= 1;
        }
    }

    // fc2 epilogue: bias + x2 residual (registers) -> NCHW out
#pragma unroll
    for (int j = 0; j < 4; j++) {
        int col = warp_n * 32 + j * 8 + 2 * t;
#pragma unroll
        for (int h = 0; h < 2; h++) {
            int row = m0 + warp_m * 16 + g + h * 8;
            int b = row >> 12;
            int n = row & (NTOK - 1);
            float r0 = acc2[j][2 * h]     + b2v[col]     + acc[j][2 * h];
            float r1 = acc2[j][2 * h + 1] + b2v[col + 1] + acc[j][2 * h + 1];
            C[((size_t)(b * CH) + col) * NTOK + n] = r0;
            C[((size_t)(b * CH) + col + 1) * NTOK + n] = r1;
        }
    }
}

// ---------------- flash attention (R9: 2-buf, ones-column l, 4 CTA/SM) ---
__global__ __launch_bounds__(256, 4)
void attn_mma_kernel() {
    __shared__ __nv_bfloat16 Ks[2][64][40];   // [buf][key][dim]
    __shared__ __nv_bfloat16 VT[2][40][72];   // [buf][dim][key]; dims 32..39: ones+zeros

    int bh = blockIdx.y;
    int b  = bh >> 2;
    int h  = bh & 3;
    int q0 = blockIdx.x * 128;
    int tid  = threadIdx.x;
    int warp = tid >> 5;
    int lane = tid & 31;
    int g = lane >> 2;
    int t = lane & 3;

    for (int idx = tid; idx < 2 * 8 * 72; idx += 256) {
        int bu = idx / (8 * 72);
        int rr = (idx / 72) & 7;
        int cc = idx % 72;
        VT[bu][32 + rr][cc] = __float2bfloat16(rr == 0 ? 1.0f : 0.0f);
    }

    unsigned qa[2][4];
    {
        const __nv_bfloat16* qp0 =
            g_qkv + (size_t)(b * NTOK + q0 + warp * 16 + g) * (3 * CH) + h * HD;
        const __nv_bfloat16* qp1 = qp0 + (size_t)8 * (3 * CH);
#pragma unroll
        for (int kk = 0; kk < 2; kk++) {
            qa[kk][0] = *(const unsigned*)(qp0 + kk * 16 + 2 * t);
            qa[kk][1] = *(const unsigned*)(qp1 + kk * 16 + 2 * t);
            qa[kk][2] = *(const unsigned*)(qp0 + kk * 16 + 2 * t + 8);
            qa[kk][3] = *(const unsigned*)(qp1 + kk * 16 + 2 * t + 8);
        }
    }

    int lkey = tid >> 2, lpart = tid & 3;
    int ld   = tid >> 3, lc    = tid & 7;
    const __nv_bfloat16* kgm =
        g_qkv + (size_t)(b * NTOK + lkey) * (3 * CH) + CH + h * HD + lpart * 8;
    const __nv_bfloat16* vgm =
        g_vT + ((size_t)bh * HD + ld) * NTOK + lc * 8;
    unsigned ksdst[2], vtdst[2];
    ksdst[0] = smem_u32(&Ks[0][lkey][lpart * 8]);
    ksdst[1] = smem_u32(&Ks[1][lkey][lpart * 8]);
    vtdst[0] = smem_u32(&VT[0][ld][lc * 8]);
    vtdst[1] = smem_u32(&VT[1][ld][lc * 8]);

    int q2 = lane >> 3, r8 = lane & 7;
    unsigned ks_lm[2], vt_lm[2], v1_lm[2];
    ks_lm[0] = smem_u32(&Ks[0][8 * (q2 >> 1) + r8][8 * (q2 & 1)]);
    ks_lm[1] = ks_lm[0] + 64 * 40 * 2;
    vt_lm[0] = smem_u32(&VT[0][8 * (q2 >> 1) + r8][8 * (q2 & 1)]);
    vt_lm[1] = vt_lm[0] + 40 * 72 * 2;
    v1_lm[0] = smem_u32(&VT[0][32 + r8][16 * (q2 >> 1) + 8 * (q2 & 1)]);
    v1_lm[1] = v1_lm[0] + 40 * 72 * 2;

    CP16(ksdst[0], kgm);
    CP16(vtdst[0], vgm);
    CPCOMMIT();

    float oc[5][4] = {};
    int buf = 0;

    for (int j0 = 0; j0 < NTOK; j0 += 64) {
        CPWAIT0();
        __syncthreads();
        if (j0 + 64 < NTOK) {
            int nb = buf ^ 1;
            CP16(ksdst[nb], kgm + (size_t)(j0 + 64) * (3 * CH));
            CP16(vtdst[nb], vgm + j0 + 64);
            CPCOMMIT();
        }
        unsigned kb = ks_lm[buf];
        unsigned vb = vt_lm[buf];
        unsigned v1 = v1_lm[buf];

        unsigned pa[4][4];
#pragma unroll
        for (int jp = 0; jp < 4; jp++) {
            unsigned f0[4], f1[4];
            LDSM4(f0[0], f0[1], f0[2], f0[3], kb + jp * 1280);
            LDSM4(f1[0], f1[1], f1[2], f1[3], kb + jp * 1280 + 32);
#pragma unroll
            for (int jj = 0; jj < 2; jj++) {
                float s4[4] = {0.f, 0.f, 0.f, 0.f};
                mma16816(s4, qa[0], f0[2 * jj], f0[2 * jj + 1]);
                mma16816(s4, qa[1], f1[2 * jj], f1[2 * jj + 1]);
                __nv_bfloat162 lo = __floats2bfloat162_rn(s4[0], s4[1]);
                __nv_bfloat162 hi = __floats2bfloat162_rn(s4[2], s4[3]);
                pa[jp][2 * jj]     = ex2b(*(unsigned*)&lo);
                pa[jp][2 * jj + 1] = ex2b(*(unsigned*)&hi);
            }
        }

#pragma unroll
        for (int kk = 0; kk < 4; kk++) {
#pragma unroll
            for (int jdp = 0; jdp < 2; jdp++) {
                unsigned m[4];
                LDSM4(m[0], m[1], m[2], m[3], vb + jdp * 2304 + kk * 32);
                mma16816(oc[2 * jdp],     pa[kk], m[0], m[1]);
                mma16816(oc[2 * jdp + 1], pa[kk], m[2], m[3]);
            }
        }
#pragma unroll
        for (int kkp = 0; kkp < 2; kkp++) {
            unsigned m[4];
            LDSM4(m[0], m[1], m[2], m[3], v1 + kkp * 64);
            mma16816(oc[4], pa[2 * kkp],     m[0], m[1]);
            mma16816(oc[4], pa[2 * kkp + 1], m[2], m[3]);
        }
        buf ^= 1;
    }

    float l0 = __shfl_sync(0xffffffffu, oc[4][0], lane & ~3);
    float l1 = __shfl_sync(0xffffffffu, oc[4][2], lane & ~3);
    float inv0 = 1.0f / l0;
    float inv1 = 1.0f / l1;

    __nv_bfloat16* op0 = g_attn + (size_t)(b * NTOK + q0 + warp * 16 + g) * CH + h * HD;
    __nv_bfloat16* op1 = op0 + (size_t)8 * CH;
#pragma unroll
    for (int jd = 0; jd < 4; jd++) {
        __nv_bfloat162 r0 = __floats2bfloat162_rn(oc[jd][0] * inv0, oc[jd][1] * inv0);
        __nv_bfloat162 r1 = __floats2bfloat162_rn(oc[jd][2] * inv1, oc[jd][3] * inv1);
        *(__nv_bfloat162*)(op0 + 8 * jd + 2 * t) = r0;
        *(__nv_bfloat162*)(op1 + 8 * jd + 2 * t) = r1;
    }
}

// ---------------- launch ----------------
extern "C" void kernel_launch(void* const* d_in, const int* in_sizes, int n_in,
                              void* d_out, int out_size) {
    const float* x      = (const float*)d_in[0];
    const float* ln1_w  = (const float*)d_in[1];
    const float* ln1_b  = (const float*)d_in[2];
    const float* qkv_w  = (const float*)d_in[3];
    const float* proj_w = (const float*)d_in[4];
    const float* proj_b = (const float*)d_in[5];
    const float* ln2_w  = (const float*)d_in[6];
    const float* ln2_b  = (const float*)d_in[7];
    const float* fc1_w  = (const float*)d_in[8];
    const float* fc1_b  = (const float*)d_in[9];
    const float* fc2_w  = (const float*)d_in[10];
    const float* fc2_b  = (const float*)d_in[11];
    float* out = (float*)d_out;

    void *p_xln, *p_xtok, *p_attn, *p_wqkv;
    cudaGetSymbolAddress(&p_xln,  g_xln);
    cudaGetSymbolAddress(&p_xtok, g_xtok);
    cudaGetSymbolAddress(&p_attn, g_attn);
    cudaGetSymbolAddress(&p_wqkv, g_wqkv);
    __nv_bfloat16* xln  = (__nv_bfloat16*)p_xln;
    float*         xtok = (float*)p_xtok;
    __nv_bfloat16* attn = (__nv_bfloat16*)p_attn;
    __nv_bfloat16* wqkv = (__nv_bfloat16*)p_wqkv;

    cudaFuncSetAttribute(tail_kernel,
                         cudaFuncAttributeMaxDynamicSharedMemorySize, TAIL_SMEM);

    // 1. LN1 (NCHW -> token-major bf16 + raw fp32 copy) + weights->bf16
    ln1_kernel<<<1024, 256>>>(x, ln1_w, ln1_b, qkv_w, proj_w, fc1_w, fc2_w);

    // 2. QKV gemm (tensor cores) -> q/k in g_qkv, v in g_vT
    gemm_qkv<<<dim3(3 * CH / 64, M_ROWS / 128), 256>>>(xln, wqkv, CH);

    // 3. flash attention -> g_attn bf16
    attn_mma_kernel<<<dim3(NTOK / 128, BATCH * HEADS), 256>>>();

    // 4. fused tail: proj + res + LN2 + fc1 + gelu + fc2 + res -> out NCHW
    tail_kernel<<<M_ROWS / 32, 256, TAIL_SMEM>>>(
        attn, proj_b, xtok, ln2_w, ln2_b, fc1_b, fc2_b, out);
}

// round 17
// speedup vs baseline: 1.0429x; 1.0429x over previous
#include <cuda_runtime.h>
#include <cuda_bf16.h>
#include <math.h>

#define BATCH 4
#define CH 128
#define NTOK 4096            // H*W
#define M_ROWS (BATCH*NTOK)  // 16384
#define HEADS 4
#define HD 32
#define HIDDEN 256
#define EPS 1e-5f

// q pre-scale: (1/sqrt(32)) * log2(e)  -> softmax done in exp2 domain
#define QSC (0.17677669529663689f * 1.4426950408889634f)

// ---------------- scratch (device globals; no allocation) ----------------
__device__ __nv_bfloat16  g_xln [M_ROWS * CH];
__device__ float          g_xtok[M_ROWS * CH];
__device__ __nv_bfloat16  g_qkv [M_ROWS * 3 * CH];
__device__ __nv_bfloat16  g_vT  [BATCH * HEADS * HD * NTOK];
__device__ __nv_bfloat16  g_attn[M_ROWS * CH];
__device__ __nv_bfloat16  g_wqkv[3 * CH * CH];
__device__ __nv_bfloat16  g_wproj[CH * CH];
__device__ __nv_bfloat16  g_wfc1[HIDDEN * CH];
__device__ __nv_bfloat16  g_wfc2[CH * HIDDEN];

__device__ __forceinline__ unsigned ex2b(unsigned x) {
    unsigned r;
    asm("ex2.approx.ftz.bf16x2 %0, %1;" : "=r"(r) : "r"(x));
    return r;
}

__device__ __forceinline__ unsigned smem_u32(const void* p) {
    return (unsigned)__cvta_generic_to_shared(p);
}

#define CP16(dst, src) \
    asm volatile("cp.async.cg.shared.global [%0], [%1], 16;" :: "r"(dst), "l"(src))
#define CPCOMMIT() asm volatile("cp.async.commit_group;")
#define CPWAIT0()  asm volatile("cp.async.wait_group 0;")

#define LDSM4(r0, r1, r2, r3, addr) \
    asm volatile("ldmatrix.sync.aligned.m8n8.x4.shared.b16 {%0,%1,%2,%3}, [%4];" \
                 : "=r"(r0), "=r"(r1), "=r"(r2), "=r"(r3) : "r"(addr))

__device__ __forceinline__ void mma16816(float d[4], const unsigned a[4],
                                         unsigned b0, unsigned b1) {
    asm volatile(
        "mma.sync.aligned.m16n8k16.row.col.f32.bf16.bf16.f32 "
        "{%0,%1,%2,%3}, {%4,%5,%6,%7}, {%8,%9}, {%0,%1,%2,%3};"
        : "+f"(d[0]), "+f"(d[1]), "+f"(d[2]), "+f"(d[3])
        : "r"(a[0]), "r"(a[1]), "r"(a[2]), "r"(a[3]), "r"(b0), "r"(b1));
}

// ---------------- LN1 (+ fused weight fp32->bf16 conversion) -------------
__global__ void ln1_kernel(const float* __restrict__ x,
                           const float* __restrict__ w,
                           const float* __restrict__ bgain,
                           const float* __restrict__ qkv_w,
                           const float* __restrict__ proj_w,
                           const float* __restrict__ fc1_w,
                           const float* __restrict__ fc2_w) {
    if (blockIdx.x >= 512) {
        int i = (blockIdx.x - 512) * 256 + threadIdx.x;
        if (i < 49152)       g_wqkv[i]          = __float2bfloat16(qkv_w[i]);
        else if (i < 65536)  g_wproj[i - 49152] = __float2bfloat16(proj_w[i - 49152]);
        else if (i < 98304)  g_wfc1[i - 65536]  = __float2bfloat16(fc1_w[i - 65536]);
        else if (i < 131072) g_wfc2[i - 98304]  = __float2bfloat16(fc2_w[i - 98304]);
        return;
    }

    __shared__ float s[CH][33];
    __shared__ float ps[8][32], pq[8][32];
    __shared__ float mu_s[32], rs_s[32];

    int b  = blockIdx.x >> 7;
    int n0 = (blockIdx.x & 127) * 32;
    int tx = threadIdx.x & 31;
    int ty = threadIdx.x >> 5;

    const float* xb = x + (size_t)b * CH * NTOK + n0;
    float sum = 0.f, sq = 0.f;
#pragma unroll
    for (int c = ty; c < CH; c += 8) {
        float v = xb[(size_t)c * NTOK + tx];
        s[c][tx] = v;
        sum += v; sq += v * v;
    }
    ps[ty][tx] = sum; pq[ty][tx] = sq;
    __syncthreads();
    if (ty == 0) {
        float S = 0.f, Q = 0.f;
#pragma unroll
        for (int i = 0; i < 8; i++) { S += ps[i][tx]; Q += pq[i][tx]; }
        float mu  = S * (1.0f / CH);
        float var = Q * (1.0f / CH) - mu * mu;
        mu_s[tx] = mu;
        rs_s[tx] = rsqrtf(var + EPS);
    }
    __syncthreads();
    __nv_bfloat16* out = g_xln + ((size_t)b * NTOK + n0) * CH;
    float* outraw = g_xtok + ((size_t)b * NTOK + n0) * CH;
    for (int idx = threadIdx.x; idx < 32 * CH; idx += 256) {
        int t = idx >> 7, c = idx & 127;
        float raw = s[c][t];
        outraw[idx] = raw;
        out[idx] = __float2bfloat16((raw - mu_s[t]) * rs_s[t] * w[c] + bgain[c]);
    }
}

// ---------------- QKV tensor-core GEMM (cp.async double-buffered) --------
#define GA_STRIDE (128 * 40 * 2)
#define GW_STRIDE (64 * 40 * 2)

__global__ __launch_bounds__(256)
void gemm_qkv(const __nv_bfloat16* __restrict__ A,
              const __nv_bfloat16* __restrict__ W, int K) {
    __shared__ __nv_bfloat16 As[2][128][40];
    __shared__ __nv_bfloat16 Ws[2][64][40];

    int m0 = blockIdx.y * 128;
    int n0 = blockIdx.x * 64;
    int tid  = threadIdx.x;
    int warp = tid >> 5;
    int lane = tid & 31;
    int g = lane >> 2;
    int t = lane & 3;
    int warp_m = warp >> 1;
    int warp_n = warp & 1;

    float acc[2][4][4];
#pragma unroll
    for (int i = 0; i < 2; i++)
#pragma unroll
        for (int j = 0; j < 4; j++)
#pragma unroll
            for (int c = 0; c < 4; c++) acc[i][j][c] = 0.f;

    int arow = tid >> 2, achk = tid & 3;
    const __nv_bfloat16* ag0 = A + (size_t)(m0 + arow) * K + achk * 8;
    const __nv_bfloat16* ag1 = A + (size_t)(m0 + arow + 64) * K + achk * 8;
    const __nv_bfloat16* wg  = W + (size_t)(n0 + arow) * K + achk * 8;
    unsigned asd = smem_u32(&As[0][arow][achk * 8]);
    unsigned wsd = smem_u32(&Ws[0][arow][achk * 8]);

    CP16(asd, ag0);
    CP16(asd + 64 * 80, ag1);
    CP16(wsd, wg);
    CPCOMMIT();

    int buf = 0;
    for (int k0 = 0; k0 < K; k0 += 32) {
        CPWAIT0();
        __syncthreads();
        if (k0 + 32 < K) {
            int nb = buf ^ 1;
            CP16(asd + nb * GA_STRIDE, ag0 + k0 + 32);
            CP16(asd + nb * GA_STRIDE + 64 * 80, ag1 + k0 + 32);
            CP16(wsd + nb * GW_STRIDE, wg + k0 + 32);
            CPCOMMIT();
        }

#pragma unroll
        for (int kk = 0; kk < 2; kk++) {
            unsigned af[2][4];
#pragma unroll
            for (int i = 0; i < 2; i++) {
                int r = warp_m * 32 + i * 16 + g;
                af[i][0] = *(const unsigned*)&As[buf][r][kk * 16 + 2 * t];
                af[i][1] = *(const unsigned*)&As[buf][r + 8][kk * 16 + 2 * t];
                af[i][2] = *(const unsigned*)&As[buf][r][kk * 16 + 2 * t + 8];
                af[i][3] = *(const unsigned*)&As[buf][r + 8][kk * 16 + 2 * t + 8];
            }
#pragma unroll
            for (int j = 0; j < 4; j++) {
                int wr = warp_n * 32 + j * 8 + g;
                unsigned b0 = *(const unsigned*)&Ws[buf][wr][kk * 16 + 2 * t];
                unsigned b1 = *(const unsigned*)&Ws[buf][wr][kk * 16 + 2 * t + 8];
                mma16816(acc[0][j], af[0], b0, b1);
                mma16816(acc[1][j], af[1], b0, b1);
            }
        }
        buf ^= 1;
    }

#pragma unroll
    for (int i = 0; i < 2; i++) {
#pragma unroll
        for (int j = 0; j < 4; j++) {
            int col = n0 + warp_n * 32 + j * 8 + 2 * t;
#pragma unroll
            for (int half = 0; half < 2; half++) {
                int row = m0 + warp_m * 32 + i * 16 + g + half * 8;
                float v0 = acc[i][j][2 * half + 0];
                float v1 = acc[i][j][2 * half + 1];
                int b = row >> 12;
                int n = row & (NTOK - 1);
                if (col < CH) {
                    __nv_bfloat162 p = __floats2bfloat162_rn(v0 * QSC, v1 * QSC);
                    *(__nv_bfloat162*)&g_qkv[(size_t)row * (3 * CH) + col] = p;
                } else if (col < 2 * CH) {
                    __nv_bfloat162 p = __floats2bfloat162_rn(v0, v1);
                    *(__nv_bfloat162*)&g_qkv[(size_t)row * (3 * CH) + col] = p;
                } else {
                    int hh = (col - 2 * CH) >> 5;
                    int d  = (col - 2 * CH) & 31;
                    size_t base = (((size_t)(b * HEADS + hh)) * HD + d) * NTOK + n;
                    g_vT[base]        = __float2bfloat16(v0);
                    g_vT[base + NTOK] = __float2bfloat16(v1);
                }
            }
        }
    }
}

// ---------------- fused tail (BM=64, R15 + resx smem prefetch) -----------
// One block owns 64 token rows end-to-end. xln, H, x2, and (new) the xtok
// residual tile never hit the epilogue critical path. Dynamic smem:
//   [0, 40960)       R1: weights dbuf (proj As1+Wsp / fc1 Ws1 / fc2 Ws2)
//   [40960, 43008)   red_s/red_q
//   [43008, 60416)   xln_s [64][136] bf16
//   [60416, 94208)   Hs [64][264] bf16  (aliased early by resx_s [64][128] f32)
#define TAIL_SMEM 94208
#define PA_STRIDE (64 * 40 * 2)
#define PW_STRIDE (128 * 40 * 2)
#define WS1_STRIDE (256 * 40 * 2)
#define WS2_STRIDE (128 * 40 * 2)
#define XSTR 136
#define HSTR 264

__global__ __launch_bounds__(256, 2)
void tail_kernel(const __nv_bfloat16* __restrict__ Aattn,
                 const float* __restrict__ pbias,
                 const float* __restrict__ resx,     // xtok fp32
                 const float* __restrict__ w2,       // ln2 w
                 const float* __restrict__ b2,       // ln2 b
                 const float* __restrict__ b1,       // fc1 bias
                 const float* __restrict__ b2v,      // fc2 bias
                 float* __restrict__ C) {
    extern __shared__ char dsm[];
    __nv_bfloat16* As1  = (__nv_bfloat16*)dsm;               // proj A [2][64][40]
    __nv_bfloat16* Wsp  = (__nv_bfloat16*)(dsm + 10240);     // proj W [2][128][40]
    __nv_bfloat16* Ws1  = (__nv_bfloat16*)dsm;               // fc1 W [2][256][40]
    __nv_bfloat16* Ws2  = (__nv_bfloat16*)dsm;               // fc2 W [2][128][40]
    float* red_s = (float*)(dsm + 40960);                    // [64][2]
    float* red_q = (float*)(dsm + 41984);                    // [64][2]
    __nv_bfloat16* xln_s = (__nv_bfloat16*)(dsm + 43008);    // [64][136]
    __nv_bfloat16* Hs    = (__nv_bfloat16*)(dsm + 60416);    // [64][264]
    float* resx_s = (float*)(dsm + 60416);                   // [64][128] (aliases Hs)

    int m0 = blockIdx.x * 64;
    int tid  = threadIdx.x;
    int warp = tid >> 5;
    int lane = tid & 31;
    int g = lane >> 2;
    int t = lane & 3;
    int warp_m = warp >> 1;   // 0..3
    int warp_n = warp & 1;    // 0..1

    int arow = tid >> 2, achk = tid & 3;

    // per-thread loader bases for each weight set
    const __nv_bfloat16* w1g = g_wfc1 + (size_t)arow * CH + achk * 8;
    unsigned ws1d = smem_u32(Ws1 + arow * 40 + achk * 8);
    const __nv_bfloat16* w2g = g_wfc2 + (size_t)arow * HIDDEN + achk * 8;
    unsigned ws2d = smem_u32(Ws2 + arow * 40 + achk * 8);

    // ================= phase 1: proj GEMM =================
    float acc[8][4];
#pragma unroll
    for (int j = 0; j < 8; j++)
#pragma unroll
        for (int c = 0; c < 4; c++) acc[j][c] = 0.f;

    {
        const __nv_bfloat16* ag  = Aattn + (size_t)(m0 + arow) * CH + achk * 8;
        const __nv_bfloat16* wg0 = g_wproj + (size_t)arow * CH + achk * 8;
        const __nv_bfloat16* wg1 = g_wproj + (size_t)(arow + 64) * CH + achk * 8;
        unsigned asd = smem_u32(As1 + arow * 40 + achk * 8);
        unsigned wsd = smem_u32(Wsp + arow * 40 + achk * 8);

        CP16(asd, ag);
        CP16(wsd, wg0);
        CP16(wsd + 64 * 80, wg1);
        // prefetch residual tile into resx_s (aliases Hs; consumed in the
        // proj epilogue, long before Hs is written in the fc1 epilogue)
#pragma unroll
        for (int i = 0; i < 8; i++) {
            int idx = tid + i * 256;
            int rr = idx >> 5, cc = idx & 31;
            CP16(smem_u32(resx_s + rr * 128 + cc * 4),
                 resx + (size_t)(m0 + rr) * CH + cc * 4);
        }
        CPCOMMIT();

        int buf = 0;
        for (int k0 = 0; k0 < CH; k0 += 32) {
            CPWAIT0();
            __syncthreads();
            if (k0 + 32 < CH) {
                int nb = buf ^ 1;
                CP16(asd + nb * PA_STRIDE, ag + k0 + 32);
                CP16(wsd + nb * PW_STRIDE, wg0 + k0 + 32);
                CP16(wsd + nb * PW_STRIDE + 64 * 80, wg1 + k0 + 32);
                CPCOMMIT();
            }
#pragma unroll
            for (int kk = 0; kk < 2; kk++) {
                unsigned af[4];
                const __nv_bfloat16* Ab = As1 + (size_t)buf * (64 * 40);
                int r = warp_m * 16 + g;
                af[0] = *(const unsigned*)&Ab[r * 40 + kk * 16 + 2 * t];
                af[1] = *(const unsigned*)&Ab[(r + 8) * 40 + kk * 16 + 2 * t];
                af[2] = *(const unsigned*)&Ab[r * 40 + kk * 16 + 2 * t + 8];
                af[3] = *(const unsigned*)&Ab[(r + 8) * 40 + kk * 16 + 2 * t + 8];
                const __nv_bfloat16* Wb = Wsp + (size_t)buf * (128 * 40);
#pragma unroll
                for (int j = 0; j < 8; j++) {
                    int wr = warp_n * 64 + j * 8 + g;
                    unsigned b0 = *(const unsigned*)&Wb[wr * 40 + kk * 16 + 2 * t];
                    unsigned b1f = *(const unsigned*)&Wb[wr * 40 + kk * 16 + 2 * t + 8];
                    mma16816(acc[j], af, b0, b1f);
                }
            }
            buf ^= 1;
        }
    }

    // hoisted fc1 stage-0 prologue: retire proj's reads of R1, then load
    __syncthreads();
#pragma unroll
    for (int i = 0; i < 4; i++)
        CP16(ws1d + i * 64 * 80, w1g + (size_t)i * 64 * CH);
    CPCOMMIT();

    // ---- proj epilogue: +bias +res(smem) -> acc (x2 in regs), LN2 -> xln_s
    float s[2] = {0.f, 0.f}, q[2] = {0.f, 0.f};
#pragma unroll
    for (int j = 0; j < 8; j++) {
        int col = warp_n * 64 + j * 8 + 2 * t;
#pragma unroll
        for (int h = 0; h < 2; h++) {
            int rl = warp_m * 16 + g + h * 8;
            float2 rv = *(const float2*)&resx_s[rl * 128 + col];
            float r0 = acc[j][2 * h]     + pbias[col]     + rv.x;
            float r1 = acc[j][2 * h + 1] + pbias[col + 1] + rv.y;
            acc[j][2 * h]     = r0;
            acc[j][2 * h + 1] = r1;
            s[h] += r0 + r1;
            q[h] += r0 * r0 + r1 * r1;
        }
    }
#pragma unroll
    for (int h = 0; h < 2; h++) {
        s[h] += __shfl_xor_sync(0xffffffffu, s[h], 1);
        s[h] += __shfl_xor_sync(0xffffffffu, s[h], 2);
        q[h] += __shfl_xor_sync(0xffffffffu, q[h], 1);
        q[h] += __shfl_xor_sync(0xffffffffu, q[h], 2);
    }
    if (t == 0) {
#pragma unroll
        for (int h = 0; h < 2; h++) {
            int rl = warp_m * 16 + g + h * 8;
            red_s[rl * 2 + warp_n] = s[h];
            red_q[rl * 2 + warp_n] = q[h];
        }
    }
    __syncthreads();

    float mu[2], rs[2];
#pragma unroll
    for (int h = 0; h < 2; h++) {
        int rl = warp_m * 16 + g + h * 8;
        float S = red_s[rl * 2] + red_s[rl * 2 + 1];
        float Q = red_q[rl * 2] + red_q[rl * 2 + 1];
        mu[h] = S * (1.0f / CH);
        float var = Q * (1.0f / CH) - mu[h] * mu[h];
        rs[h] = rsqrtf(var + EPS);
    }

#pragma unroll
    for (int j = 0; j < 8; j++) {
        int col = warp_n * 64 + j * 8 + 2 * t;
        float2 wv = *(const float2*)&w2[col];
        float2 bv = *(const float2*)&b2[col];
#pragma unroll
        for (int h = 0; h < 2; h++) {
            int rl  = warp_m * 16 + g + h * 8;
            float r0 = acc[j][2 * h];
            float r1 = acc[j][2 * h + 1];
            __nv_bfloat162 p = __floats2bfloat162_rn(
                (r0 - mu[h]) * rs[h] * wv.x + bv.x,
                (r1 - mu[h]) * rs[h] * wv.y + bv.y);
            *(__nv_bfloat162*)&xln_s[rl * XSTR + col] = p;
        }
    }
    __syncthreads();   // xln_s complete; resx_s dead -> Hs region reusable

    // ================= phase 2: fc1 + gelu -> Hs =================
    float acc1[16][4];
#pragma unroll
    for (int j = 0; j < 16; j++)
#pragma unroll
        for (int c = 0; c < 4; c++) acc1[j][c] = 0.f;

    {
        int buf = 0;
        for (int k0 = 0; k0 < CH; k0 += 32) {
            CPWAIT0();
            __syncthreads();
            if (k0 + 32 < CH) {
                int nb = buf ^ 1;
#pragma unroll
                for (int i = 0; i < 4; i++)
                    CP16(ws1d + nb * WS1_STRIDE + i * 64 * 80,
                         w1g + (size_t)i * 64 * CH + k0 + 32);
                CPCOMMIT();
            }
#pragma unroll
            for (int kk = 0; kk < 2; kk++) {
                unsigned af[4];
                int r = warp_m * 16 + g;
                int kc = k0 + kk * 16 + 2 * t;
                af[0] = *(const unsigned*)&xln_s[r * XSTR + kc];
                af[1] = *(const unsigned*)&xln_s[(r + 8) * XSTR + kc];
                af[2] = *(const unsigned*)&xln_s[r * XSTR + kc + 8];
                af[3] = *(const unsigned*)&xln_s[(r + 8) * XSTR + kc + 8];
                const __nv_bfloat16* Wb = Ws1 + (size_t)buf * (256 * 40);
#pragma unroll
                for (int j = 0; j < 16; j++) {
                    int wr = warp_n * 128 + j * 8 + g;
                    unsigned b0 = *(const unsigned*)&Wb[wr * 40 + kk * 16 + 2 * t];
                    unsigned b1f = *(const unsigned*)&Wb[wr * 40 + kk * 16 + 2 * t + 8];
                    mma16816(acc1[j], af, b0, b1f);
                }
            }
            buf ^= 1;
        }
    }

    // hoisted fc2 stage-0 prologue: Ws2 slot0 (0..10240) disjoint from
    // fc1 slot1 (20480..40960) still being read.
    CP16(ws2d, w2g);
    CP16(ws2d + 64 * 80, w2g + (size_t)64 * HIDDEN);
    CPCOMMIT();

    // fc1 epilogue: bias + gelu -> Hs
#pragma unroll
    for (int j = 0; j < 16; j++) {
        int col = warp_n * 128 + j * 8 + 2 * t;
#pragma unroll
        for (int h = 0; h < 2; h++) {
            int rl = warp_m * 16 + g + h * 8;
            float r0 = acc1[j][2 * h]     + b1[col];
            float r1 = acc1[j][2 * h + 1] + b1[col + 1];
            r0 = 0.5f * r0 * (1.0f + erff(r0 * 0.70710678118654752f));
            r1 = 0.5f * r1 * (1.0f + erff(r1 * 0.70710678118654752f));
            __nv_bfloat162 p = __floats2bfloat162_rn(r0, r1);
            *(__nv_bfloat162*)&Hs[rl * HSTR + col] = p;
        }
    }
    __syncthreads();   // Hs complete

    // ================= phase 3: fc2 + b2 + x2(regs) -> out =================
    float acc2[8][4];
#pragma unroll
    for (int j = 0; j < 8; j++)
#pragma unroll
        for (int c = 0; c < 4; c++) acc2[j][c] = 0.f;

    {
        int buf = 0;
        for (int k0 = 0; k0 < HIDDEN; k0 += 32) {
            CPWAIT0();
            __syncthreads();
            if (k0 + 32 < HIDDEN) {
                int nb = buf ^ 1;
                CP16(ws2d + nb * WS2_STRIDE, w2g + k0 + 32);
                CP16(ws2d + nb * WS2_STRIDE + 64 * 80,
                     w2g + (size_t)64 * HIDDEN + k0 + 32);
                CPCOMMIT();
            }
#pragma unroll
            for (int kk = 0; kk < 2; kk++) {
                unsigned af[4];
                int r = warp_m * 16 + g;
                int kc = k0 + kk * 16 + 2 * t;
                af[0] = *(const unsigned*)&Hs[r * HSTR + kc];
                af[1] = *(const unsigned*)&Hs[(r + 8) * HSTR + kc];
                af[2] = *(const unsigned*)&Hs[r * HSTR + kc + 8];
                af[3] = *(const unsigned*)&Hs[(r + 8) * HSTR + kc + 8];
                const __nv_bfloat16* Wb = Ws2 + (size_t)buf * (128 * 40);
#pragma unroll
                for (int j = 0; j < 8; j++) {
                    int wr = warp_n * 64 + j * 8 + g;
                    unsigned b0 = *(const unsigned*)&Wb[wr * 40 + kk * 16 + 2 * t];
                    unsigned b1f = *(const unsigned*)&Wb[wr * 40 + kk * 16 + 2 * t + 8];
                    mma16816(acc2[j], af, b0, b1f);
                }
            }
            buf ^= 1;
        }
    }

    // fc2 epilogue: bias + x2 residual (registers) -> NCHW out
#pragma unroll
    for (int j = 0; j < 8; j++) {
        int col = warp_n * 64 + j * 8 + 2 * t;
#pragma unroll
        for (int h = 0; h < 2; h++) {
            int row = m0 + warp_m * 16 + g + h * 8;
            int b = row >> 12;
            int n = row & (NTOK - 1);
            float r0 = acc2[j][2 * h]     + b2v[col]     + acc[j][2 * h];
            float r1 = acc2[j][2 * h + 1] + b2v[col + 1] + acc[j][2 * h + 1];
            C[((size_t)(b * CH) + col) * NTOK + n] = r0;
            C[((size_t)(b * CH) + col + 1) * NTOK + n] = r1;
        }
    }
}

// ---------------- flash attention (R9: 2-buf, ones-column l, 4 CTA/SM) ---
__global__ __launch_bounds__(256, 4)
void attn_mma_kernel() {
    __shared__ __nv_bfloat16 Ks[2][64][40];   // [buf][key][dim]
    __shared__ __nv_bfloat16 VT[2][40][72];   // [buf][dim][key]; dims 32..39: ones+zeros

    int bh = blockIdx.y;
    int b  = bh >> 2;
    int h  = bh & 3;
    int q0 = blockIdx.x * 128;
    int tid  = threadIdx.x;
    int warp = tid >> 5;
    int lane = tid & 31;
    int g = lane >> 2;
    int t = lane & 3;

    for (int idx = tid; idx < 2 * 8 * 72; idx += 256) {
        int bu = idx / (8 * 72);
        int rr = (idx / 72) & 7;
        int cc = idx % 72;
        VT[bu][32 + rr][cc] = __float2bfloat16(rr == 0 ? 1.0f : 0.0f);
    }

    unsigned qa[2][4];
    {
        const __nv_bfloat16* qp0 =
            g_qkv + (size_t)(b * NTOK + q0 + warp * 16 + g) * (3 * CH) + h * HD;
        const __nv_bfloat16* qp1 = qp0 + (size_t)8 * (3 * CH);
#pragma unroll
        for (int kk = 0; kk < 2; kk++) {
            qa[kk][0] = *(const unsigned*)(qp0 + kk * 16 + 2 * t);
            qa[kk][1] = *(const unsigned*)(qp1 + kk * 16 + 2 * t);
            qa[kk][2] = *(const unsigned*)(qp0 + kk * 16 + 2 * t + 8);
            qa[kk][3] = *(const unsigned*)(qp1 + kk * 16 + 2 * t + 8);
        }
    }

    int lkey = tid >> 2, lpart = tid & 3;
    int ld   = tid >> 3, lc    = tid & 7;
    const __nv_bfloat16* kgm =
        g_qkv + (size_t)(b * NTOK + lkey) * (3 * CH) + CH + h * HD + lpart * 8;
    const __nv_bfloat16* vgm =
        g_vT + ((size_t)bh * HD + ld) * NTOK + lc * 8;
    unsigned ksdst[2], vtdst[2];
    ksdst[0] = smem_u32(&Ks[0][lkey][lpart * 8]);
    ksdst[1] = smem_u32(&Ks[1][lkey][lpart * 8]);
    vtdst[0] = smem_u32(&VT[0][ld][lc * 8]);
    vtdst[1] = smem_u32(&VT[1][ld][lc * 8]);

    int q2 = lane >> 3, r8 = lane & 7;
    unsigned ks_lm[2], vt_lm[2], v1_lm[2];
    ks_lm[0] = smem_u32(&Ks[0][8 * (q2 >> 1) + r8][8 * (q2 & 1)]);
    ks_lm[1] = ks_lm[0] + 64 * 40 * 2;
    vt_lm[0] = smem_u32(&VT[0][8 * (q2 >> 1) + r8][8 * (q2 & 1)]);
    vt_lm[1] = vt_lm[0] + 40 * 72 * 2;
    v1_lm[0] = smem_u32(&VT[0][32 + r8][16 * (q2 >> 1) + 8 * (q2 & 1)]);
    v1_lm[1] = v1_lm[0] + 40 * 72 * 2;

    CP16(ksdst[0], kgm);
    CP16(vtdst[0], vgm);
    CPCOMMIT();

    float oc[5][4] = {};
    int buf = 0;

    for (int j0 = 0; j0 < NTOK; j0 += 64) {
        CPWAIT0();
        __syncthreads();
        if (j0 + 64 < NTOK) {
            int nb = buf ^ 1;
            CP16(ksdst[nb], kgm + (size_t)(j0 + 64) * (3 * CH));
            CP16(vtdst[nb], vgm + j0 + 64);
            CPCOMMIT();
        }
        unsigned kb = ks_lm[buf];
        unsigned vb = vt_lm[buf];
        unsigned v1 = v1_lm[buf];

        unsigned pa[4][4];
#pragma unroll
        for (int jp = 0; jp < 4; jp++) {
            unsigned f0[4], f1[4];
            LDSM4(f0[0], f0[1], f0[2], f0[3], kb + jp * 1280);
            LDSM4(f1[0], f1[1], f1[2], f1[3], kb + jp * 1280 + 32);
#pragma unroll
            for (int jj = 0; jj < 2; jj++) {
                float s4[4] = {0.f, 0.f, 0.f, 0.f};
                mma16816(s4, qa[0], f0[2 * jj], f0[2 * jj + 1]);
                mma16816(s4, qa[1], f1[2 * jj], f1[2 * jj + 1]);
                __nv_bfloat162 lo = __floats2bfloat162_rn(s4[0], s4[1]);
                __nv_bfloat162 hi = __floats2bfloat162_rn(s4[2], s4[3]);
                pa[jp][2 * jj]     = ex2b(*(unsigned*)&lo);
                pa[jp][2 * jj + 1] = ex2b(*(unsigned*)&hi);
            }
        }

#pragma unroll
        for (int kk = 0; kk < 4; kk++) {
#pragma unroll
            for (int jdp = 0; jdp < 2; jdp++) {
                unsigned m[4];
                LDSM4(m[0], m[1], m[2], m[3], vb + jdp * 2304 + kk * 32);
                mma16816(oc[2 * jdp],     pa[kk], m[0], m[1]);
                mma16816(oc[2 * jdp + 1], pa[kk], m[2], m[3]);
            }
        }
#pragma unroll
        for (int kkp = 0; kkp < 2; kkp++) {
            unsigned m[4];
            LDSM4(m[0], m[1], m[2], m[3], v1 + kkp * 64);
            mma16816(oc[4], pa[2 * kkp],     m[0], m[1]);
            mma16816(oc[4], pa[2 * kkp + 1], m[2], m[3]);
        }
        buf ^= 1;
    }

    float l0 = __shfl_sync(0xffffffffu, oc[4][0], lane & ~3);
    float l1 = __shfl_sync(0xffffffffu, oc[4][2], lane & ~3);
    float inv0 = 1.0f / l0;
    float inv1 = 1.0f / l1;

    __nv_bfloat16* op0 = g_attn + (size_t)(b * NTOK + q0 + warp * 16 + g) * CH + h * HD;
    __nv_bfloat16* op1 = op0 + (size_t)8 * CH;
#pragma unroll
    for (int jd = 0; jd < 4; jd++) {
        __nv_bfloat162 r0 = __floats2bfloat162_rn(oc[jd][0] * inv0, oc[jd][1] * inv0);
        __nv_bfloat162 r1 = __floats2bfloat162_rn(oc[jd][2] * inv1, oc[jd][3] * inv1);
        *(__nv_bfloat162*)(op0 + 8 * jd + 2 * t) = r0;
        *(__nv_bfloat162*)(op1 + 8 * jd + 2 * t) = r1;
    }
}

// ---------------- launch ----------------
extern "C" void kernel_launch(void* const* d_in, const int* in_sizes, int n_in,
                              void* d_out, int out_size) {
    const float* x      = (const float*)d_in[0];
    const float* ln1_w  = (const float*)d_in[1];
    const float* ln1_b  = (const float*)d_in[2];
    const float* qkv_w  = (const float*)d_in[3];
    const float* proj_w = (const float*)d_in[4];
    const float* proj_b = (const float*)d_in[5];
    const float* ln2_w  = (const float*)d_in[6];
    const float* ln2_b  = (const float*)d_in[7];
    const float* fc1_w  = (const float*)d_in[8];
    const float* fc1_b  = (const float*)d_in[9];
    const float* fc2_w  = (const float*)d_in[10];
    const float* fc2_b  = (const float*)d_in[11];
    float* out = (float*)d_out;

    void *p_xln, *p_xtok, *p_attn, *p_wqkv;
    cudaGetSymbolAddress(&p_xln,  g_xln);
    cudaGetSymbolAddress(&p_xtok, g_xtok);
    cudaGetSymbolAddress(&p_attn, g_attn);
    cudaGetSymbolAddress(&p_wqkv, g_wqkv);
    __nv_bfloat16* xln  = (__nv_bfloat16*)p_xln;
    float*         xtok = (float*)p_xtok;
    __nv_bfloat16* attn = (__nv_bfloat16*)p_attn;
    __nv_bfloat16* wqkv = (__nv_bfloat16*)p_wqkv;

    cudaFuncSetAttribute(tail_kernel,
                         cudaFuncAttributeMaxDynamicSharedMemorySize, TAIL_SMEM);

    // 1. LN1 (NCHW -> token-major bf16 + raw fp32 copy) + weights->bf16
    ln1_kernel<<<1024, 256>>>(x, ln1_w, ln1_b, qkv_w, proj_w, fc1_w, fc2_w);

    // 2. QKV gemm (tensor cores) -> q/k in g_qkv, v in g_vT
    gemm_qkv<<<dim3(3 * CH / 64, M_ROWS / 128), 256>>>(xln, wqkv, CH);

    // 3. flash attention -> g_attn bf16
    attn_mma_kernel<<<dim3(NTOK / 128, BATCH * HEADS), 256>>>();

    // 4. fused tail: proj + res + LN2 + fc1 + gelu + fc2 + res -> out NCHW
    tail_kernel<<<M_ROWS / 64, 256, TAIL_SMEM>>>(
        attn, proj_b, xtok, ln2_w, ln2_b, fc1_b, fc2_b, out);
}